// round 10
// baseline (speedup 1.0000x reference)
#include <cuda_runtime.h>
#include <math.h>
#include <stdint.h>

#define Bn 16
#define Cn 3
#define Hn 512
#define Wn 512
#define HW (Hn * Wn)           // 262144
#define CHW (Cn * HW)          // 786432
#define NTOT (Bn * Cn * HW)    // 12582912

#define TW 64                  // owned tile width
#define TH 32                  // owned tile height
#define RT_W 72                // rt cols: idx k = gcol w0-4+k (owned col c -> idx c+4)
#define HTH (TH + 2)           // 34 halo rows
#define NTHREADS 256
#define NW 8                   // warps per block

#define GX (Wn / TW)           // 8
#define GY (Hn / TH)           // 16
#define BPB (GX * GY)          // 128
#define NBLK (BPB * Bn)        // 2048

// smem layout (dynamic): rt[HTH*RT_W] then stage[NW][2][9][72]
#define RT_FLOATS (HTH * RT_W)            // 2448
#define STG_BUF   (9 * 72)                // 648 floats per buffer
#define STG_WARP  (2 * STG_BUF)           // 1296
#define SMEM_FLOATS (RT_FLOATS + NW * STG_WARP)
#define SMEM_BYTES  (SMEM_FLOATS * 4)     // 51264

__device__ float g_part[3][NBLK];   // RAW-scale partials, written exactly once
__device__ unsigned int g_count;    // zero-init; last block resets to 0

__device__ __forceinline__ int reflect(int i, int n) {
    return (i < 0) ? -i : ((i >= n) ? 2 * n - 2 - i : i);
}
__device__ __forceinline__ float sgnsel(float rs, float re) {
    return (rs < re) ? __int_as_float(__float_as_int(rs) | 0x80000000u) : rs;
}
__device__ __forceinline__ uint32_t smem_u32(const void* p) {
    return (uint32_t)__cvta_generic_to_shared(p);
}
__device__ __forceinline__ void cp16(uint32_t dst, const float* src) {
    asm volatile("cp.async.cg.shared.global [%0], [%1], 16;" :: "r"(dst), "l"(src));
}
__device__ __forceinline__ void cp4(uint32_t dst, const float* src) {
    asm volatile("cp.async.ca.shared.global [%0], [%1], 4;" :: "r"(dst), "l"(src));
}
__device__ __forceinline__ void cp_commit() {
    asm volatile("cp.async.commit_group;" ::: "memory");
}
template<int N> __device__ __forceinline__ void cp_wait() {
    asm volatile("cp.async.wait_group %0;" :: "n"(N) : "memory");
}

// ---------------------------------------------------------------------------
__global__ __launch_bounds__(NTHREADS) void fused_kernel(
    const float* __restrict__ sr,
    const float* __restrict__ srema,
    const float* __restrict__ hr,
    float* __restrict__ out)
{
    extern __shared__ float smem[];
    float* rt = smem;

    const int tid  = threadIdx.x;
    const int lane = tid & 31;
    const int warp = tid >> 5;
    float* stg = smem + RT_FLOATS + warp * STG_WARP;
    const uint32_t stg_u32 = smem_u32(stg);

    const int w0 = blockIdx.x * TW;
    const int h0 = blockIdx.y * TH;
    const int b  = blockIdx.z;
    const int base = b * CHW;

    // 9 streams: hr ch0-2, sr ch0-2, srema ch0-2
    const float* ins[9] = { hr, hr + HW, hr + 2 * HW,
                            sr, sr + HW, sr + 2 * HW,
                            srema, srema + HW, srema + 2 * HW };

    // One "special" vector per row handled as 4 scalar cp.asyncs (covers column
    // reflection at image edges; for interior blocks it's just plain columns).
    int spec_v; int4 sc;
    if (blockIdx.x == 0)           { spec_v = 0;  sc = make_int4(4, 3, 2, 1); }
    else if (blockIdx.x == GX - 1) { spec_v = 17; sc = make_int4(510, 509, 508, 507); }
    else                           { spec_v = 0;  sc = make_int4(w0-4, w0-3, w0-2, w0-1); }

    // lanes 0-16: one 16B vector each (the 17 non-special vecs);
    // lanes 17-25: stream (lane-17)'s special vec as 4 scalar copies.
    const int v_reg = (lane < 17) ? (lane + (lane >= spec_v ? 1 : 0)) : -1;

    auto prefetch = [&](int row, int buf) {
        const int gh = reflect(h0 - 1 + row, Hn);
        const int rowbase = base + gh * Wn;
        const uint32_t dstb = stg_u32 + (uint32_t)(buf * (STG_BUF * 4));
        if (v_reg >= 0) {
            const int goff = rowbase + (w0 - 4) + 4 * v_reg;
            const uint32_t dv = dstb + (uint32_t)(4 * v_reg * 4);
#pragma unroll
            for (int s = 0; s < 9; ++s)
                cp16(dv + (uint32_t)(s * 72 * 4), ins[s] + goff);
        } else if (lane < 26) {
#pragma unroll
            for (int s = 0; s < 9; ++s) {
                if (lane == 17 + s) {
                    const uint32_t d = dstb + (uint32_t)((s * 72 + 4 * spec_v) * 4);
                    cp4(d,      ins[s] + rowbase + sc.x);
                    cp4(d + 4,  ins[s] + rowbase + sc.y);
                    cp4(d + 8,  ins[s] + rowbase + sc.z);
                    cp4(d + 12, ins[s] + rowbase + sc.w);
                }
            }
        }
        cp_commit();
    };

    auto compute_row = [&](int row, int buf) {
        const float* st = stg + buf * STG_BUF;
        float* rrow = rt + row * RT_W;
#pragma unroll
        for (int t = 0; t < 3; ++t) {
            const int j = lane + t * 32;
            if (j < 72) {
                float a0 = st[0*72+j], a1 = st[1*72+j], a2 = st[2*72+j];
                float s0 = st[3*72+j], s1 = st[4*72+j], s2 = st[5*72+j];
                float e0 = st[6*72+j], e1 = st[7*72+j], e2 = st[8*72+j];
                float rs = fabsf(a0-s0) + fabsf(a1-s1) + fabsf(a2-s2);
                float re = fabsf(a0-e0) + fabsf(a1-e1) + fabsf(a2-e2);
                rrow[j] = sgnsel(rs, re);
            }
        }
    };

    // --- Phase 1: warp-autonomous double-buffered async pipeline -------------
    const int nrows = (HTH - warp + NW - 1) / NW;   // rows: warp, warp+8, ...
    prefetch(warp, 0);
    for (int i = 0; i < nrows; ++i) {
        if (i + 1 < nrows) { prefetch(warp + (i + 1) * NW, (i + 1) & 1); cp_wait<1>(); }
        else               { cp_wait<0>(); }
        __syncwarp();
        compute_row(warp + i * NW, i & 1);
    }
    __syncthreads();

    // --- Phase 2: 3x3 unbiased local variance (R6 form) ----------------------
    float lsum = 0.f, lsq = 0.f, lS = 0.f;
#pragma unroll
    for (int k = 0; k < (TW * TH) / NTHREADS; ++k) {
        const int p   = tid + k * NTHREADS;
        const int row = p >> 6;
        const int col = p & 63;
        const float* r0 = rt + row * RT_W + col + 3;
        const float* r1 = r0 + RT_W;
        const float* r2 = r1 + RT_W;

        float c_s = r1[1];
        float v0 = fabsf(r0[0]), v1 = fabsf(r0[1]), v2 = fabsf(r0[2]);
        float v3 = fabsf(r1[0]), v4 = fabsf(c_s),   v5 = fabsf(r1[2]);
        float v6 = fabsf(r2[0]), v7 = fabsf(r2[1]), v8 = fabsf(r2[2]);

        float s  = v0 + v1 + v2 + v3 + v4 + v5 + v6 + v7 + v8;
        float sq = v0*v0 + v1*v1 + v2*v2 + v3*v3 + v4*v4
                 + v5*v5 + v6*v6 + v7*v7 + v8*v8;
        float lv = (sq - s * s * (1.0f / 9.0f)) * (1.0f / 8.0f);

        lS   += signbit(c_s) ? 0.0f : fabsf(lv) * v4;
        lsum += v4;
        lsq  += v4 * v4;
    }

    // --- Block reduction -------------------------------------------------------
    __shared__ float wsum[NW], wsq[NW], wS[NW];
#pragma unroll
    for (int o = 16; o > 0; o >>= 1) {
        lsum += __shfl_down_sync(0xffffffffu, lsum, o);
        lsq  += __shfl_down_sync(0xffffffffu, lsq,  o);
        lS   += __shfl_down_sync(0xffffffffu, lS,   o);
    }
    if (lane == 0) { wsum[warp] = lsum; wsq[warp] = lsq; wS[warp] = lS; }
    __syncthreads();

    __shared__ bool isLast;
    if (tid == 0) {
        float a = 0.f, cc = 0.f, d = 0.f;
#pragma unroll
        for (int i = 0; i < NW; ++i) { a += wsum[i]; cc += wsq[i]; d += wS[i]; }
        const int bid = blockIdx.x + GX * blockIdx.y + BPB * blockIdx.z;
        g_part[0][bid] = a;
        g_part[1][bid] = cc;
        g_part[2][bid] = d;
        __threadfence();
        unsigned prev = atomicAdd(&g_count, 1u);
        isLast = (prev == NBLK - 1);
    }
    __syncthreads();

    // --- Last block: per-batch patch weight + final loss ------------------------
    if (isLast) {
        if (tid == 0) g_count = 0;   // reset for next graph replay
        __shared__ float sres[Bn];
#pragma unroll
        for (int j = 0; j < 2; ++j) {
            const int bb  = warp * 2 + j;
            const int idx = bb * BPB + lane * 4;
            float s = 0.f, sq = 0.f, S = 0.f;
#pragma unroll
            for (int e = 0; e < 4; ++e) {
                s  += __ldcg(&g_part[0][idx + e]);
                sq += __ldcg(&g_part[1][idx + e]);
                S  += __ldcg(&g_part[2][idx + e]);
            }
#pragma unroll
            for (int o = 16; o > 0; o >>= 1) {
                s  += __shfl_down_sync(0xffffffffu, s,  o);
                sq += __shfl_down_sync(0xffffffffu, sq, o);
                S  += __shfl_down_sync(0xffffffffu, S,  o);
            }
            if (lane == 0) {
                const float n = (float)HW;
                float var = (sq - s * s / n) / (n - 1.0f);   // raw-scale variance
                float w = (var > 0.0f) ? exp2f(0.2f * log2f(var)) : 0.0f;
                sres[bb] = w * S;
            }
        }
        __syncthreads();
        if (tid == 0) {
            float acc = 0.f;
#pragma unroll
            for (int i = 0; i < Bn; ++i) acc += sres[i];
            // loss = 255^(-2.4)/NTOT * sum_b var_raw^0.2 * S_raw
            double Kd = pow(255.0, -2.4) / (double)NTOT;
            out[0] = (float)((double)acc * Kd);
        }
    }
}

// ---------------------------------------------------------------------------
extern "C" void kernel_launch(void* const* d_in, const int* in_sizes, int n_in,
                              void* d_out, int out_size) {
    const float* sr    = (const float*)d_in[0];
    const float* srema = (const float*)d_in[1];
    const float* hr    = (const float*)d_in[2];
    float* out = (float*)d_out;

    cudaFuncSetAttribute(fused_kernel,
                         cudaFuncAttributeMaxDynamicSharedMemorySize, SMEM_BYTES);

    dim3 blk(NTHREADS, 1, 1);
    dim3 grd(GX, GY, Bn);
    fused_kernel<<<grd, blk, SMEM_BYTES>>>(sr, srema, hr, out);
}

// round 11
// speedup vs baseline: 1.5339x; 1.5339x over previous
#include <cuda_runtime.h>
#include <math.h>

#define Bn 16
#define Cn 3
#define Hn 512
#define Wn 512
#define HW (Hn * Wn)           // 262144
#define CHW (Cn * HW)          // 786432
#define NTOT (Bn * Cn * HW)    // 12582912

// ---- K1 config: pure streaming residual ----
#define K1_THREADS 256
#define K1_PX_PER_THREAD 8     // 2 float4 groups
#define K1_PX_PER_BLOCK (K1_THREADS * K1_PX_PER_THREAD)   // 2048
#define K1_BPB (HW / K1_PX_PER_BLOCK)                     // 128
#define K1_NBLK (K1_BPB * Bn)                             // 2048

// ---- K2 config: stencil over r_det ----
#define TW 64
#define TH 32
#define HTW 72                 // smem cols: gcol w0-4+k
#define HTH (TH + 2)           // 34
#define VPR 18
#define NITEMS (HTH * VPR)     // 612
#define K2_THREADS 256
#define GX (Wn / TW)           // 8
#define GY (Hn / TH)           // 16
#define K2_BPB (GX * GY)       // 128
#define K2_NBLK (K2_BPB * Bn)  // 2048

// Scratch (static device globals; no runtime allocation)
__device__ float g_rdet[Bn * HW];            // signed residual (sign bit = mask)
__device__ float g_p1sum[K1_NBLK];           // per-K1-block sum(r_raw)
__device__ float g_p1sq[K1_NBLK];            // per-K1-block sum(r_raw^2)
__device__ float g_p2S[K2_NBLK];             // per-K2-block sum(|lv|*r*mask)
__device__ unsigned int g_count;             // zero-init; last K2 block resets

__device__ __forceinline__ int reflect(int i, int n) {
    return (i < 0) ? -i : ((i >= n) ? 2 * n - 2 - i : i);
}
__device__ __forceinline__ float sgnsel(float rs, float re) {
    return (rs < re) ? __int_as_float(__float_as_int(rs) | 0x80000000u) : rs;
}

// ===========================================================================
// K1: streaming signed residual + per-block patch-sum partials.
// Pure unit-stride float4 streaming, no tiles, no branches.
// ===========================================================================
__global__ __launch_bounds__(K1_THREADS) void residual_kernel(
    const float* __restrict__ sr,
    const float* __restrict__ srema,
    const float* __restrict__ hr)
{
    const int tid   = threadIdx.x;
    const int bid   = blockIdx.x;
    const int b     = bid >> 7;           // / K1_BPB
    const int chunk = bid & 127;          // % K1_BPB
    const int base  = b * CHW;
    const int p0    = chunk * K1_PX_PER_BLOCK;

    float lsum = 0.f, lsq = 0.f;
#pragma unroll
    for (int k = 0; k < 2; ++k) {
        const int p  = p0 + (tid + k * K1_THREADS) * 4;
        const int ix = base + p;

        float4 h0v = __ldg((const float4*)(hr    + ix));
        float4 s0v = __ldg((const float4*)(sr    + ix));
        float4 e0v = __ldg((const float4*)(srema + ix));
        float4 h1v = __ldg((const float4*)(hr    + ix + HW));
        float4 s1v = __ldg((const float4*)(sr    + ix + HW));
        float4 e1v = __ldg((const float4*)(srema + ix + HW));
        float4 h2v = __ldg((const float4*)(hr    + ix + 2 * HW));
        float4 s2v = __ldg((const float4*)(sr    + ix + 2 * HW));
        float4 e2v = __ldg((const float4*)(srema + ix + 2 * HW));

        float4 o4;
        {
            float rs = fabsf(h0v.x-s0v.x) + fabsf(h1v.x-s1v.x) + fabsf(h2v.x-s2v.x);
            float re = fabsf(h0v.x-e0v.x) + fabsf(h1v.x-e1v.x) + fabsf(h2v.x-e2v.x);
            o4.x = sgnsel(rs, re); lsum += rs; lsq += rs * rs;
        }
        {
            float rs = fabsf(h0v.y-s0v.y) + fabsf(h1v.y-s1v.y) + fabsf(h2v.y-s2v.y);
            float re = fabsf(h0v.y-e0v.y) + fabsf(h1v.y-e1v.y) + fabsf(h2v.y-e2v.y);
            o4.y = sgnsel(rs, re); lsum += rs; lsq += rs * rs;
        }
        {
            float rs = fabsf(h0v.z-s0v.z) + fabsf(h1v.z-s1v.z) + fabsf(h2v.z-s2v.z);
            float re = fabsf(h0v.z-e0v.z) + fabsf(h1v.z-e1v.z) + fabsf(h2v.z-e2v.z);
            o4.z = sgnsel(rs, re); lsum += rs; lsq += rs * rs;
        }
        {
            float rs = fabsf(h0v.w-s0v.w) + fabsf(h1v.w-s1v.w) + fabsf(h2v.w-s2v.w);
            float re = fabsf(h0v.w-e0v.w) + fabsf(h1v.w-e1v.w) + fabsf(h2v.w-e2v.w);
            o4.w = sgnsel(rs, re); lsum += rs; lsq += rs * rs;
        }
        *(float4*)(g_rdet + b * HW + p) = o4;
    }

    // block reduction -> per-block partials (written exactly once, no zeroing)
    __shared__ float wsum[8], wsq[8];
#pragma unroll
    for (int o = 16; o > 0; o >>= 1) {
        lsum += __shfl_down_sync(0xffffffffu, lsum, o);
        lsq  += __shfl_down_sync(0xffffffffu, lsq,  o);
    }
    const int warp = tid >> 5;
    if ((tid & 31) == 0) { wsum[warp] = lsum; wsq[warp] = lsq; }
    __syncthreads();
    if (tid == 0) {
        float a = 0.f, c = 0.f;
#pragma unroll
        for (int i = 0; i < 8; ++i) { a += wsum[i]; c += wsq[i]; }
        g_p1sum[bid] = a;
        g_p1sq[bid]  = c;
    }
}

// ===========================================================================
// K2: 3x3 unbiased local variance over |r_det|, S partials, last-block finalize.
// ===========================================================================
__global__ __launch_bounds__(K2_THREADS) void loss_kernel(float* __restrict__ out)
{
    __shared__ float rt[HTH * HTW];

    const int tid = threadIdx.x;
    const int w0  = blockIdx.x * TW;
    const int h0  = blockIdx.y * TH;
    const int b   = blockIdx.z;
    const float* __restrict__ rd = g_rdet + b * HW;

    // --- load halo tile (single array, light) --------------------------------
    const bool interior = (blockIdx.x > 0 && blockIdx.x < GX - 1);
    for (int t = tid; t < NITEMS; t += K2_THREADS) {
        const int ty  = t / VPR;
        const int v   = t - ty * VPR;
        const int gh  = reflect(h0 - 1 + ty, Hn);
        const int gw0 = w0 - 4 + 4 * v;
        float4 o4;
        if (interior || (gw0 >= 0 && gw0 + 3 < Wn)) {
            o4 = __ldg((const float4*)(rd + gh * Wn + gw0));
        } else {
            o4.x = __ldg(rd + gh * Wn + reflect(gw0,     Wn));
            o4.y = __ldg(rd + gh * Wn + reflect(gw0 + 1, Wn));
            o4.z = __ldg(rd + gh * Wn + reflect(gw0 + 2, Wn));
            o4.w = __ldg(rd + gh * Wn + reflect(gw0 + 3, Wn));
        }
        *(float4*)(rt + ty * HTW + 4 * v) = o4;
    }
    __syncthreads();

    // --- stencil --------------------------------------------------------------
    float lS = 0.f;
#pragma unroll
    for (int k = 0; k < (TW * TH) / K2_THREADS; ++k) {
        const int p   = tid + k * K2_THREADS;
        const int row = p >> 6;
        const int col = p & 63;
        const float* r0 = rt + row * HTW + col + 3;
        const float* r1 = r0 + HTW;
        const float* r2 = r1 + HTW;

        float c_s = r1[1];
        float v0 = fabsf(r0[0]), v1 = fabsf(r0[1]), v2 = fabsf(r0[2]);
        float v3 = fabsf(r1[0]), v4 = fabsf(c_s),   v5 = fabsf(r1[2]);
        float v6 = fabsf(r2[0]), v7 = fabsf(r2[1]), v8 = fabsf(r2[2]);

        float s  = v0 + v1 + v2 + v3 + v4 + v5 + v6 + v7 + v8;
        float sq = v0*v0 + v1*v1 + v2*v2 + v3*v3 + v4*v4
                 + v5*v5 + v6*v6 + v7*v7 + v8*v8;
        float lv = (sq - s * s * (1.0f / 9.0f)) * (1.0f / 8.0f);

        lS += signbit(c_s) ? 0.0f : fabsf(lv) * v4;
    }

    __shared__ float wS[8];
#pragma unroll
    for (int o = 16; o > 0; o >>= 1)
        lS += __shfl_down_sync(0xffffffffu, lS, o);
    const int warp = tid >> 5;
    if ((tid & 31) == 0) wS[warp] = lS;
    __syncthreads();

    __shared__ bool isLast;
    if (tid == 0) {
        float d = 0.f;
#pragma unroll
        for (int i = 0; i < 8; ++i) d += wS[i];
        const int bid2 = blockIdx.x + GX * blockIdx.y + K2_BPB * blockIdx.z;
        g_p2S[bid2] = d;
        __threadfence();
        unsigned prev = atomicAdd(&g_count, 1u);
        isLast = (prev == K2_NBLK - 1);
    }
    __syncthreads();

    // --- finalize: patch weights + loss ---------------------------------------
    if (isLast) {
        if (tid == 0) g_count = 0;   // reset for graph replay
        __shared__ float sres[Bn];
        const int warp2 = tid >> 5;
        const int lane  = tid & 31;
#pragma unroll
        for (int j = 0; j < 2; ++j) {
            const int bb = warp2 * 2 + j;
            float s = 0.f, sq = 0.f, S = 0.f;
#pragma unroll
            for (int e = 0; e < 4; ++e) {
                const int i1 = bb * K1_BPB + lane * 4 + e;   // K1 partials
                const int i2 = bb * K2_BPB + lane * 4 + e;   // K2 partials
                s  += __ldcg(&g_p1sum[i1]);
                sq += __ldcg(&g_p1sq[i1]);
                S  += __ldcg(&g_p2S[i2]);
            }
#pragma unroll
            for (int o = 16; o > 0; o >>= 1) {
                s  += __shfl_down_sync(0xffffffffu, s,  o);
                sq += __shfl_down_sync(0xffffffffu, sq, o);
                S  += __shfl_down_sync(0xffffffffu, S,  o);
            }
            if (lane == 0) {
                const float n = (float)HW;
                float var = (sq - s * s / n) / (n - 1.0f);   // raw scale
                float w = (var > 0.0f) ? exp2f(0.2f * log2f(var)) : 0.0f;
                sres[bb] = w * S;
            }
        }
        __syncthreads();
        if (tid == 0) {
            float acc = 0.f;
#pragma unroll
            for (int i = 0; i < Bn; ++i) acc += sres[i];
            // loss = 255/NTOT * sum_b (k^2 var)^0.2 * k^3 S, k=1/255
            //      = 255^(-2.4)/NTOT * sum_b var_raw^0.2 * S_raw
            double Kd = pow(255.0, -2.4) / (double)NTOT;
            out[0] = (float)((double)acc * Kd);
        }
    }
}

// ---------------------------------------------------------------------------
extern "C" void kernel_launch(void* const* d_in, const int* in_sizes, int n_in,
                              void* d_out, int out_size) {
    const float* sr    = (const float*)d_in[0];
    const float* srema = (const float*)d_in[1];
    const float* hr    = (const float*)d_in[2];
    float* out = (float*)d_out;

    residual_kernel<<<K1_NBLK, K1_THREADS>>>(sr, srema, hr);
    dim3 blk(K2_THREADS, 1, 1);
    dim3 grd(GX, GY, Bn);
    loss_kernel<<<grd, blk>>>(out);
}